// round 13
// baseline (speedup 1.0000x reference)
#include <cuda_runtime.h>
#include <cuda_fp16.h>
#include <cstdint>

// Problem constants
#define H     80
#define B     4096
#define T     512
#define NROW  32            // batch rows per CTA (2 streams x 16)
#define NCTA  128
#define NTHR  320           // 10 warps; warp w owns m-tiles {2w, 2w+1}

// A (weights) fp16 K-major [gr=320][k=KA], gr = 4*j + gate (i,f,g,o interleaved)
// k: [0,80)=w_hh1, [80,160)=w_ih2, [160,240)=w_hh2 ; padded to KA
#define KA    248           // stride in halves; 496B/16=31 (odd) -> conflict-free ldmatrix
#define KB    168           // h buffer stride in halves; 336B/16=21 (odd)
#define GS    324           // gates f32 stride ([r][gr] transposed)

#define A_BYTES (320 * KA * 2)     // 158720
#define B_BYTES (NROW * KB * 2)    // 10752

// smem offsets (bytes)
#define SM_W    0
#define SM_B    (A_BYTES)
#define SM_G    (SM_B + B_BYTES)
#define SM_BIAS (SM_G + NROW * GS * 4)
#define SM_W1X  (SM_BIAS + 2560)
#define SM_WLIN (SM_W1X + 1280)
#define SM_X    (SM_WLIN + 320)             // 2 x 32 f32
#define SM_PART (SM_X + 256)                // 2 x 64 f32
#define SMEM_TOTAL (SM_PART + 512 + 64)

__device__ __half g_Wh[320 * KA];

static __device__ __forceinline__ uint32_t smem_u32(const void *p) {
    uint32_t a;
    asm("{ .reg .u64 t; cvta.to.shared.u64 t, %1; cvt.u32.u64 %0, t; }" : "=r"(a) : "l"(p));
    return a;
}
static __device__ __forceinline__ float tanhap(float x) {
    float y; asm("tanh.approx.f32 %0, %1;" : "=f"(y) : "f"(x)); return y;
}
static __device__ __forceinline__ float sigf(float x) {
    return fmaf(0.5f, tanhap(0.5f * x), 0.5f);
}

#define LDSM_X4(r0, r1, r2, r3, addr) \
    asm volatile("ldmatrix.sync.aligned.m8n8.x4.shared.b16 {%0,%1,%2,%3}, [%4];" \
                 : "=r"(r0), "=r"(r1), "=r"(r2), "=r"(r3) : "r"(addr))
#define LDSM_X2(r0, r1, addr) \
    asm volatile("ldmatrix.sync.aligned.m8n8.x2.shared.b16 {%0,%1}, [%2];" \
                 : "=r"(r0), "=r"(r1) : "r"(addr))
#define MMA16816(d, a0, a1, a2, a3, b0, b1) \
    asm volatile("mma.sync.aligned.m16n8k16.row.col.f32.f16.f16.f32 " \
                 "{%0,%1,%2,%3}, {%4,%5,%6,%7}, {%8,%9}, {%0,%1,%2,%3};" \
                 : "+f"((d)[0]), "+f"((d)[1]), "+f"((d)[2]), "+f"((d)[3]) \
                 : "r"(a0), "r"(a1), "r"(a2), "r"(a3), "r"(b0), "r"(b1))

// ---------------------------------------------------------------------------
// pack: fp16 weight image A[gr][k], gr = 4j+g, K-major
// ---------------------------------------------------------------------------
__global__ void pack_w_kernel(const float *__restrict__ whh1,
                              const float *__restrict__ wih2,
                              const float *__restrict__ whh2) {
    int idx = blockIdx.x * blockDim.x + threadIdx.x;
    if (idx >= 320 * KA) return;
    int gr = idx / KA, k = idx % KA;
    int g = gr & 3, j = gr >> 2;
    int row = g * 80 + j;
    float v = 0.0f;
    if (k < 80)       v = whh1[row * 80 + k];
    else if (k < 160) v = wih2[row * 80 + (k - 80)];
    else if (k < 240) v = whh2[row * 80 + (k - 160)];
    g_Wh[gr * KA + k] = __float2half_rn(v);
}

// ---------------------------------------------------------------------------
// gemm for ONE stream (N=16): NK k-steps; A k-offset KAOFF; bB includes the
// stream's 16-row offset. d[mtile 2][ntile 2][4].
// ---------------------------------------------------------------------------
template<int NK, int KAOFF>
static __device__ __forceinline__ void gemm_mma(uint32_t aB0, uint32_t aB1,
                                                uint32_t bB, float (&d)[2][2][4]) {
#pragma unroll
    for (int m = 0; m < 2; m++)
#pragma unroll
        for (int n = 0; n < 2; n++)
#pragma unroll
            for (int q = 0; q < 4; q++) d[m][n][q] = 0.0f;
#pragma unroll
    for (int c = 0; c < NK; c++) {
        uint32_t a0, a1, a2, a3, e0, e1, e2, e3;
        LDSM_X4(a0, a1, a2, a3, aB0 + (KAOFF + c * 16) * 2);
        LDSM_X4(e0, e1, e2, e3, aB1 + (KAOFF + c * 16) * 2);
        uint32_t b0[2], b1[2];
#pragma unroll
        for (int nt = 0; nt < 2; nt++)
            LDSM_X2(b0[nt], b1[nt], bB + nt * (8 * KB * 2) + c * 32);
#pragma unroll
        for (int nt = 0; nt < 2; nt++) {
            MMA16816(d[0][nt], a0, a1, a2, a3, b0[nt], b1[nt]);
            MMA16816(d[1][nt], e0, e1, e2, e3, b0[nt], b1[nt]);
        }
    }
}

// epilogue: D fragments -> gates smem transposed [r][gr], rows rbase..rbase+15
static __device__ __forceinline__ void epi(float *gf, const float (&d)[2][2][4],
                                           int mt0, int lid, int rbase) {
    const int g = lid >> 2, tg = lid & 3;
#pragma unroll
    for (int m = 0; m < 2; m++) {
        const int gr = (mt0 + m) * 16 + g;
#pragma unroll
        for (int nt = 0; nt < 2; nt++) {
            const int r = rbase + nt * 8 + 2 * tg;
            gf[r * GS + gr]           = d[m][nt][0];
            gf[(r + 1) * GS + gr]     = d[m][nt][1];
            gf[r * GS + gr + 8]       = d[m][nt][2];
            gf[(r + 1) * GS + gr + 8] = d[m][nt][3];
        }
    }
}

// cell for ONE stream (16 rows): layer L; thread (j=tid%80, rb=tid/80) does
// 4 rows rbase+rb*4+dr. xbuf indexed by global row (0..31). Writes h fp16.
template<int L>
static __device__ __forceinline__ void cellp(char *smem, int tid,
                                             const float *xbuf, float (&cst)[4],
                                             int rbase) {
    const int j  = tid % 80;
    const int r0 = rbase + (tid / 80) * 4;
    const float *gf = (const float *)(smem + SM_G);
    const float4 bb = ((const float4 *)(smem + SM_BIAS))[L * 80 + j];
    float4 wx = make_float4(0.f, 0.f, 0.f, 0.f);
    if (L == 0) wx = ((const float4 *)(smem + SM_W1X))[j];
    const int kk = (L == 0) ? j : (80 + j);
    __half *hb = (__half *)(smem + SM_B);
#pragma unroll
    for (int dr = 0; dr < 4; dr++) {
        const int r = r0 + dr;
        const float4 gv = *(const float4 *)(gf + r * GS + 4 * j);
        float iv = gv.x + bb.x, fv = gv.y + bb.y;
        float gg = gv.z + bb.z, ov = gv.w + bb.w;
        if (L == 0) {
            const float xr = xbuf[r];
            iv = fmaf(wx.x, xr, iv); fv = fmaf(wx.y, xr, fv);
            gg = fmaf(wx.z, xr, gg); ov = fmaf(wx.w, xr, ov);
        }
        const float cc = sigf(fv) * cst[dr] + sigf(iv) * tanhap(gg);
        cst[dr] = cc;
        hb[r * KB + kk] = __float2half_rn(sigf(ov) * tanhap(cc));
    }
}

// head partials for stream s: 64 threads (tid 256..319), 20-j chunks
static __device__ __forceinline__ void head_part(char *smem, int tid, int s) {
    if (tid < 256) return;
    const int i = tid - 256;
    const int q = i >> 4, r = i & 15;
    const __half *hb = (const __half *)(smem + SM_B);
    const float *wlin_s = (const float *)(smem + SM_WLIN);
    float ssum = 0.0f;
#pragma unroll
    for (int jj = 0; jj < 20; jj++) {
        const int j = q * 20 + jj;
        ssum = fmaf(wlin_s[j], __half2float(hb[(16 * s + r) * KB + 80 + j]), ssum);
    }
    ((float *)(smem + SM_PART))[s * 64 + q * 16 + r] = ssum;
}
// head reduce for stream s -> out[., tOut]
static __device__ __forceinline__ void head_red(char *smem, int tid, int s,
                                                float blin_v, float *out,
                                                int b0, int tOut) {
    const int i = tid - 256;
    if (tid < 256 || i >= 16) return;
    const float *part = (const float *)(smem + SM_PART) + s * 64;
    out[(b0 + 16 * s + i) * T + tOut] =
        blin_v + part[i] + part[16 + i] + part[32 + i] + part[48 + i];
}

// ---------------------------------------------------------------------------
// main kernel: two phase-shifted row streams; gemm of one overlaps cell of
// the other (tensor+LDSM vs MUFU+LDS). 4 barriers/step.
// ---------------------------------------------------------------------------
__global__ void __launch_bounds__(NTHR, 1)
lstm_mma_kernel(const float *__restrict__ input,
                const float *__restrict__ w_ih1,
                const float *__restrict__ b_ih1, const float *__restrict__ b_hh1,
                const float *__restrict__ b_ih2, const float *__restrict__ b_hh2,
                const float *__restrict__ w_lin, const float *__restrict__ b_lin,
                float *__restrict__ out) {
    extern __shared__ char smem[];
    const int tid = threadIdx.x;
    const int wid = tid >> 5;
    const int lid = tid & 31;
    const int b0  = blockIdx.x * NROW;
    const uint32_t sb = smem_u32(smem);

    // weights -> smem
    {
        const int4 *s = (const int4 *)g_Wh;
        int4 *dd = (int4 *)(smem + SM_W);
        for (int i = tid; i < A_BYTES / 16; i += NTHR) dd[i] = s[i];
    }
    // zero h buffer
    {
        int4 z = make_int4(0, 0, 0, 0);
        int4 *dd = (int4 *)(smem + SM_B);
        for (int i = tid; i < B_BYTES / 16; i += NTHR) dd[i] = z;
    }
    // biases / w1x / wlin
    {
        float *bias_s = (float *)(smem + SM_BIAS);
        float *w1x_s  = (float *)(smem + SM_W1X);
        for (int i = tid; i < 640; i += NTHR) {
            int l = i / 320, e = i % 320;
            int g = e & 3, j = e >> 2;
            int row = g * 80 + j;
            bias_s[i] = l ? (b_ih2[row] + b_hh2[row]) : (b_ih1[row] + b_hh1[row]);
        }
        for (int i = tid; i < 320; i += NTHR) {
            int g = i & 3, j = i >> 2;
            w1x_s[i] = w_ih1[g * 80 + j];
        }
        if (tid < H) ((float *)(smem + SM_WLIN))[tid] = w_lin[tid];
    }

    // per-thread ldmatrix bases
    const int mt0 = wid * 2;
    const uint32_t aRow = (uint32_t)((lid & 7) + ((lid >> 3) & 1) * 8);
    const uint32_t aK8  = (uint32_t)(((lid >> 4) & 1) * 8);
    const uint32_t aB0  = sb + SM_W + ((mt0 * 16 + aRow) * KA + aK8) * 2;
    const uint32_t aB1  = aB0 + 16 * KA * 2;
    const uint32_t bRow = (uint32_t)(lid & 7);
    const uint32_t bK8  = (uint32_t)(((lid >> 3) & 1) * 8);
    const uint32_t bB0  = sb + SM_B + (bRow * KB + bK8) * 2;          // stream 0
    const uint32_t bB1  = bB0 + 16 * KB * 2;                          // stream 1

    float *gf   = (float *)(smem + SM_G);
    float *xs   = (float *)(smem + SM_X);      // [2][32]
    const float blin_v = b_lin[0];
    const int srow = b0 + (tid & 31);

    float c1s0[4], c1s1[4], c2s0[4], c2s1[4];
#pragma unroll
    for (int q = 0; q < 4; q++) { c1s0[q] = c1s1[q] = c2s0[q] = c2s1[q] = 0.0f; }

    if (tid < NROW) xs[tid] = input[srow * T + 0];
    __syncthreads();

    for (int t = 0; t < T; t++) {
        float xnext = 0.0f;
        if (tid < NROW && t + 1 < T) xnext = input[srow * T + (t + 1)];
        const float *xb = xs + (t & 1) * 32;
        float d[2][2][4];

        // ---- PHASE A: S0.g1(t) | S1.c2(t-1) | S0.head_part(t-1) ----
        gemm_mma<5, 0>(aB0, aB1, bB0, d);
        epi(gf, d, mt0, lid, 0);
        if (t > 0) {
            cellp<1>(smem, tid, nullptr, c2s1, 16);
            head_part(smem, tid, 0);
        }
        __syncthreads();

        // ---- PHASE B: S1.g1(t) | S0.c1(t) | S0.head_red, S1.head_part ----
        gemm_mma<5, 0>(aB0, aB1, bB1, d);
        epi(gf, d, mt0, lid, 16);
        cellp<0>(smem, tid, xb, c1s0, 0);
        if (t > 0) {
            head_red(smem, tid, 0, blin_v, out, b0, t - 1);
            head_part(smem, tid, 1);
        }
        __syncthreads();

        // ---- PHASE C: S0.g2(t) | S1.c1(t) | S1.head_red ----
        gemm_mma<10, 80>(aB0, aB1, bB0, d);
        epi(gf, d, mt0, lid, 0);
        cellp<0>(smem, tid, xb, c1s1, 16);
        if (t > 0) head_red(smem, tid, 1, blin_v, out, b0, t - 1);
        __syncthreads();

        // ---- PHASE D: S1.g2(t) | S0.c2(t) | x prefetch ----
        gemm_mma<10, 80>(aB0, aB1, bB1, d);
        epi(gf, d, mt0, lid, 16);
        cellp<1>(smem, tid, nullptr, c2s0, 0);
        if (tid < NROW && t + 1 < T) xs[((t + 1) & 1) * 32 + tid] = xnext;
        __syncthreads();
    }

    // ---- epilogue: flush S1.c2(T-1) and both heads for t = T-1 ----
    cellp<1>(smem, tid, nullptr, c2s1, 16);
    head_part(smem, tid, 0);
    __syncthreads();
    head_red(smem, tid, 0, blin_v, out, b0, T - 1);
    head_part(smem, tid, 1);
    __syncthreads();
    head_red(smem, tid, 1, blin_v, out, b0, T - 1);
}

extern "C" void kernel_launch(void *const *d_in, const int *in_sizes, int n_in,
                              void *d_out, int out_size) {
    const float *input = (const float *)d_in[0];
    const float *wih1  = (const float *)d_in[1];
    const float *whh1  = (const float *)d_in[2];
    const float *bih1  = (const float *)d_in[3];
    const float *bhh1  = (const float *)d_in[4];
    const float *wih2  = (const float *)d_in[5];
    const float *whh2  = (const float *)d_in[6];
    const float *bih2  = (const float *)d_in[7];
    const float *bhh2  = (const float *)d_in[8];
    const float *wlin  = (const float *)d_in[17];
    const float *blin  = (const float *)d_in[18];

    pack_w_kernel<<<(320 * KA + 255) / 256, 256>>>(whh1, wih2, whh2);

    cudaFuncSetAttribute(lstm_mma_kernel, cudaFuncAttributeMaxDynamicSharedMemorySize,
                         SMEM_TOTAL);
    lstm_mma_kernel<<<NCTA, NTHR, SMEM_TOTAL>>>(input, wih1, bih1, bhh1, bih2, bhh2,
                                                wlin, blin, (float *)d_out);
}

// round 14
// speedup vs baseline: 1.1718x; 1.1718x over previous
#include <cuda_runtime.h>
#include <cuda_fp16.h>
#include <cstdint>

// Problem constants
#define H     80
#define B     4096
#define T     512
#define NROW  32            // batch rows per CTA
#define NCTA  128
#define NTHR  320           // 10 warps; warp w owns m-tiles {2w, 2w+1}

// A (weights) fp16 K-major [gr=320][k=KA], gr = 4*j + gate (i,f,g,o interleaved)
// k: [0,80)=w_hh1, [80,160)=w_ih2, [160,240)=w_hh2 ; padded to KA
#define KA    248           // stride in halves; 496B/16=31 (odd) -> conflict-free ldmatrix
#define KB    168           // h buffer stride in halves; 336B/16=21 (odd)
#define GS    324           // gates f32 stride ([r][gr] transposed)

#define A_BYTES (320 * KA * 2)     // 158720
#define B_BYTES (NROW * KB * 2)    // 10752

// smem offsets (bytes)
#define SM_W    0
#define SM_B    (A_BYTES)
#define SM_G    (SM_B + B_BYTES)
#define SM_BIAS (SM_G + NROW * GS * 4)
#define SM_W1X  (SM_BIAS + 2560)
#define SM_WLIN (SM_W1X + 1280)
#define SM_X    (SM_WLIN + 320)
#define SM_PART (SM_X + 256)
#define SMEM_TOTAL (SM_PART + 512 + 64)

__device__ __half g_Wh[320 * KA];

static __device__ __forceinline__ uint32_t smem_u32(const void *p) {
    uint32_t a;
    asm("{ .reg .u64 t; cvta.to.shared.u64 t, %1; cvt.u32.u64 %0, t; }" : "=r"(a) : "l"(p));
    return a;
}
static __device__ __forceinline__ float tanhap(float x) {
    float y; asm("tanh.approx.f32 %0, %1;" : "=f"(y) : "f"(x)); return y;
}
static __device__ __forceinline__ float sigf(float x) {
    return fmaf(0.5f, tanhap(0.5f * x), 0.5f);
}

#define LDSM_X4(r0, r1, r2, r3, addr) \
    asm volatile("ldmatrix.sync.aligned.m8n8.x4.shared.b16 {%0,%1,%2,%3}, [%4];" \
                 : "=r"(r0), "=r"(r1), "=r"(r2), "=r"(r3) : "r"(addr))
#define LDSM_X2(r0, r1, addr) \
    asm volatile("ldmatrix.sync.aligned.m8n8.x2.shared.b16 {%0,%1}, [%2];" \
                 : "=r"(r0), "=r"(r1) : "r"(addr))
#define MMA16816(d, a0, a1, a2, a3, b0, b1) \
    asm volatile("mma.sync.aligned.m16n8k16.row.col.f32.f16.f16.f32 " \
                 "{%0,%1,%2,%3}, {%4,%5,%6,%7}, {%8,%9}, {%0,%1,%2,%3};" \
                 : "+f"((d)[0]), "+f"((d)[1]), "+f"((d)[2]), "+f"((d)[3]) \
                 : "r"(a0), "r"(a1), "r"(a2), "r"(a3), "r"(b0), "r"(b1))

// ---------------------------------------------------------------------------
// pack: fp16 weight image A[gr][k], gr = 4j+g, K-major
// ---------------------------------------------------------------------------
__global__ void pack_w_kernel(const float *__restrict__ whh1,
                              const float *__restrict__ wih2,
                              const float *__restrict__ whh2) {
    int idx = blockIdx.x * blockDim.x + threadIdx.x;
    if (idx >= 320 * KA) return;
    int gr = idx / KA, k = idx % KA;
    int g = gr & 3, j = gr >> 2;
    int row = g * 80 + j;
    float v = 0.0f;
    if (k < 80)       v = whh1[row * 80 + k];
    else if (k < 160) v = wih2[row * 80 + (k - 80)];
    else if (k < 240) v = whh2[row * 80 + (k - 160)];
    g_Wh[gr * KA + k] = __float2half_rn(v);
}

// ---------------------------------------------------------------------------
// gemm1: K=80, A via LDSM each step (5 chunks)
// ---------------------------------------------------------------------------
static __device__ __forceinline__ void gemm1(uint32_t aB0, uint32_t aB1,
                                             uint32_t bB, float (&d)[2][4][4]) {
#pragma unroll
    for (int m = 0; m < 2; m++)
#pragma unroll
        for (int n = 0; n < 4; n++)
#pragma unroll
            for (int q = 0; q < 4; q++) d[m][n][q] = 0.0f;
#pragma unroll
    for (int c = 0; c < 5; c++) {
        uint32_t a0, a1, a2, a3, e0, e1, e2, e3;
        LDSM_X4(a0, a1, a2, a3, aB0 + c * 32);
        LDSM_X4(e0, e1, e2, e3, aB1 + c * 32);
        uint32_t b0[4], b1[4];
#pragma unroll
        for (int nt = 0; nt < 4; nt++)
            LDSM_X2(b0[nt], b1[nt], bB + nt * (8 * KB * 2) + c * 32);
#pragma unroll
        for (int nt = 0; nt < 4; nt++) {
            MMA16816(d[0][nt], a0, a1, a2, a3, b0[nt], b1[nt]);
            MMA16816(d[1][nt], e0, e1, e2, e3, b0[nt], b1[nt]);
        }
    }
}

// ---------------------------------------------------------------------------
// gemm2: K=160 (k offset 80), A fragments RESIDENT in registers (loop-invariant)
// ---------------------------------------------------------------------------
static __device__ __forceinline__ void gemm2(const uint32_t (&aF)[10][2][4],
                                             uint32_t bB, float (&d)[2][4][4]) {
#pragma unroll
    for (int m = 0; m < 2; m++)
#pragma unroll
        for (int n = 0; n < 4; n++)
#pragma unroll
            for (int q = 0; q < 4; q++) d[m][n][q] = 0.0f;
#pragma unroll
    for (int c = 0; c < 10; c++) {
        uint32_t b0[4], b1[4];
#pragma unroll
        for (int nt = 0; nt < 4; nt++)
            LDSM_X2(b0[nt], b1[nt], bB + nt * (8 * KB * 2) + c * 32);
#pragma unroll
        for (int nt = 0; nt < 4; nt++) {
            MMA16816(d[0][nt], aF[c][0][0], aF[c][0][1], aF[c][0][2], aF[c][0][3],
                     b0[nt], b1[nt]);
            MMA16816(d[1][nt], aF[c][1][0], aF[c][1][1], aF[c][1][2], aF[c][1][3],
                     b0[nt], b1[nt]);
        }
    }
}

// epilogue: D fragments -> gates smem transposed [r][gr]  (bank conflict-free)
static __device__ __forceinline__ void epi(float *gf, const float (&d)[2][4][4],
                                           int mt0, int lid) {
    const int g = lid >> 2, tg = lid & 3;
#pragma unroll
    for (int m = 0; m < 2; m++) {
        const int gr = (mt0 + m) * 16 + g;
#pragma unroll
        for (int nt = 0; nt < 4; nt++) {
            const int r = nt * 8 + 2 * tg;
            gf[r * GS + gr]           = d[m][nt][0];
            gf[(r + 1) * GS + gr]     = d[m][nt][1];
            gf[r * GS + gr + 8]       = d[m][nt][2];
            gf[(r + 1) * GS + gr + 8] = d[m][nt][3];
        }
    }
}

// cell: layer l; thread (j = tid%80) handles 8 rows; writes h fp16 into B[k]
static __device__ __forceinline__ void cellp(char *smem, int tid, int l,
                                             const float *xbuf, float (&cst)[8]) {
    const int j  = tid % 80;
    const int r0 = (tid / 80) * 8;
    const float *gf = (const float *)(smem + SM_G);
    const float4 bb = ((const float4 *)(smem + SM_BIAS))[l * 80 + j];
    float4 wx = make_float4(0.f, 0.f, 0.f, 0.f);
    if (l == 0) wx = ((const float4 *)(smem + SM_W1X))[j];
    const int kk = (l == 0) ? j : (80 + j);
    __half *hb = (__half *)(smem + SM_B);
#pragma unroll
    for (int dr = 0; dr < 8; dr++) {
        const int r = r0 + dr;
        const float4 gv = *(const float4 *)(gf + r * GS + 4 * j);
        float iv = gv.x + bb.x, fv = gv.y + bb.y;
        float gg = gv.z + bb.z, ov = gv.w + bb.w;
        if (l == 0) {
            const float xr = xbuf[r];
            iv = fmaf(wx.x, xr, iv); fv = fmaf(wx.y, xr, fv);
            gg = fmaf(wx.z, xr, gg); ov = fmaf(wx.w, xr, ov);
        }
        const float cc = sigf(fv) * cst[dr] + sigf(iv) * tanhap(gg);
        cst[dr] = cc;
        hb[r * KB + kk] = __float2half_rn(sigf(ov) * tanhap(cc));
    }
}

// ---------------------------------------------------------------------------
// main kernel
// ---------------------------------------------------------------------------
__global__ void __launch_bounds__(NTHR, 1)
lstm_mma_kernel(const float *__restrict__ input,
                const float *__restrict__ w_ih1,
                const float *__restrict__ b_ih1, const float *__restrict__ b_hh1,
                const float *__restrict__ b_ih2, const float *__restrict__ b_hh2,
                const float *__restrict__ w_lin, const float *__restrict__ b_lin,
                float *__restrict__ out) {
    extern __shared__ char smem[];
    const int tid = threadIdx.x;
    const int wid = tid >> 5;
    const int lid = tid & 31;
    const int b0  = blockIdx.x * NROW;
    const uint32_t sb = smem_u32(smem);

    // weights -> smem
    {
        const int4 *s = (const int4 *)g_Wh;
        int4 *dd = (int4 *)(smem + SM_W);
        for (int i = tid; i < A_BYTES / 16; i += NTHR) dd[i] = s[i];
    }
    // zero h buffer (h1 = h2 = 0)
    {
        int4 z = make_int4(0, 0, 0, 0);
        int4 *dd = (int4 *)(smem + SM_B);
        for (int i = tid; i < B_BYTES / 16; i += NTHR) dd[i] = z;
    }
    // biases / w1x / wlin
    {
        float *bias_s = (float *)(smem + SM_BIAS);
        float *w1x_s  = (float *)(smem + SM_W1X);
        for (int i = tid; i < 640; i += NTHR) {
            int l = i / 320, e = i % 320;
            int g = e & 3, j = e >> 2;
            int row = g * 80 + j;
            bias_s[i] = l ? (b_ih2[row] + b_hh2[row]) : (b_ih1[row] + b_hh1[row]);
        }
        for (int i = tid; i < 320; i += NTHR) {
            int g = i & 3, j = i >> 2;
            w1x_s[i] = w_ih1[g * 80 + j];
        }
        if (tid < H) ((float *)(smem + SM_WLIN))[tid] = w_lin[tid];
    }

    // per-thread ldmatrix bases
    const int mt0 = wid * 2;
    const uint32_t aRow = (uint32_t)((lid & 7) + ((lid >> 3) & 1) * 8);
    const uint32_t aK8  = (uint32_t)(((lid >> 4) & 1) * 8);
    const uint32_t aB0  = sb + SM_W + ((mt0 * 16 + aRow) * KA + aK8) * 2;
    const uint32_t aB1  = aB0 + 16 * KA * 2;
    const uint32_t bRow = (uint32_t)(lid & 7);
    const uint32_t bK8  = (uint32_t)(((lid >> 3) & 1) * 8);
    const uint32_t bB   = sb + SM_B + (bRow * KB + bK8) * 2;

    __syncthreads();

    // preload gemm2 A fragments (k = 80..240), resident across all 512 steps
    uint32_t aF[10][2][4];
#pragma unroll
    for (int c = 0; c < 10; c++) {
        LDSM_X4(aF[c][0][0], aF[c][0][1], aF[c][0][2], aF[c][0][3],
                aB0 + (80 + c * 16) * 2);
        LDSM_X4(aF[c][1][0], aF[c][1][1], aF[c][1][2], aF[c][1][3],
                aB1 + (80 + c * 16) * 2);
    }

    float *gf     = (float *)(smem + SM_G);
    float *xs     = (float *)(smem + SM_X);      // [2][32]
    float *part   = (float *)(smem + SM_PART);
    const float *wlin_s = (const float *)(smem + SM_WLIN);
    const float blin_v = b_lin[0];
    const int srow = b0 + (tid & 31);

    float c1[8], c2[8];
#pragma unroll
    for (int q = 0; q < 8; q++) { c1[q] = 0.0f; c2[q] = 0.0f; }

    if (tid < NROW) xs[tid] = input[srow * T + 0];
    __syncthreads();

    for (int t = 0; t < T; t++) {
        // issue next-step x load early (fire LDG; consumed near end of step)
        float xnext = 0.0f;
        if (tid < NROW && t + 1 < T) xnext = input[srow * T + (t + 1)];

        float d[2][4][4];

        // ----- gemm1: gates1 = W_hh1 @ h1(t-1), K = 80 -----
        gemm1(aB0, aB1, bB, d);
        epi(gf, d, mt0, lid);
        __syncthreads();                 // gates1 ready; all h1-old reads done

        cellp(smem, tid, 0, xs + (t & 1) * 32, c1);   // writes h1(t) fp16
        __syncthreads();                 // h1(t) ready

        // ----- gemm2: gates2 = [W_ih2 | W_hh2] @ [h1(t) | h2(t-1)], K = 160 -----
        gemm2(aF, bB, d);
        epi(gf, d, mt0, lid);
        if (tid < NROW && t + 1 < T) xs[((t + 1) & 1) * 32 + tid] = xnext;
        __syncthreads();                 // gates2 ready; all h2-old reads done

        cellp(smem, tid, 1, nullptr, c2);             // writes h2(t) fp16
        __syncthreads();                 // h2(t) ready

        // head: out[b, t] = w_lin . h2(t) + b_lin
        if (tid < 128) {
            const int q = tid >> 5, r = tid & 31;
            const __half *hb = (const __half *)(smem + SM_B);
            float s = 0.0f;
#pragma unroll
            for (int jj = 0; jj < 20; jj++) {
                const int j = q * 20 + jj;
                s = fmaf(wlin_s[j], __half2float(hb[r * KB + 80 + j]), s);
            }
            part[q * 32 + r] = s;
        }
        __syncthreads();
        if (tid < NROW)
            out[srow * T + t] =
                blin_v + part[tid] + part[32 + tid] + part[64 + tid] + part[96 + tid];
        __syncthreads();                 // part consumed; next step may overwrite
    }
}

extern "C" void kernel_launch(void *const *d_in, const int *in_sizes, int n_in,
                              void *d_out, int out_size) {
    const float *input = (const float *)d_in[0];
    const float *wih1  = (const float *)d_in[1];
    const float *whh1  = (const float *)d_in[2];
    const float *bih1  = (const float *)d_in[3];
    const float *bhh1  = (const float *)d_in[4];
    const float *wih2  = (const float *)d_in[5];
    const float *whh2  = (const float *)d_in[6];
    const float *bih2  = (const float *)d_in[7];
    const float *bhh2  = (const float *)d_in[8];
    const float *wlin  = (const float *)d_in[17];
    const float *blin  = (const float *)d_in[18];

    pack_w_kernel<<<(320 * KA + 255) / 256, 256>>>(whh1, wih2, whh2);

    cudaFuncSetAttribute(lstm_mma_kernel, cudaFuncAttributeMaxDynamicSharedMemorySize,
                         SMEM_TOTAL);
    lstm_mma_kernel<<<NCTA, NTHR, SMEM_TOTAL>>>(input, wih1, bih1, bhh1, bih2, bhh2,
                                                wlin, blin, (float *)d_out);
}

// round 15
// speedup vs baseline: 1.2623x; 1.0772x over previous
#include <cuda_runtime.h>
#include <cuda_fp16.h>
#include <cstdint>

// Problem constants
#define H     80
#define B     4096
#define T     512
#define NROW  32
#define NCTA  128
#define NTHR  320           // 10 warps; warp w owns m-tiles {2w, 2w+1}

#define KA1   88            // w_hh1 smem stride (halves); 176B/16=11 odd -> conflict-free
#define KB    168           // h buffer stride (halves); 336B/16=21 odd
#define GS    324           // gates f32 stride ([r][gr] transposed)

#define W1_BYTES (320 * KA1 * 2)   // 56320
#define B_BYTES  (NROW * KB * 2)   // 10752
#define G_BYTES  (NROW * GS * 4)   // 41472

// smem offsets (bytes)
#define SM_W1   0
#define SM_B    (SM_W1 + W1_BYTES)          // 56320
#define SM_G1   (SM_B + B_BYTES)            // 67072  (also init staging, spans G1+G2)
#define SM_G2   (SM_G1 + G_BYTES)           // 108544
#define SM_BIAS (SM_G2 + G_BYTES)           // 150016
#define SM_W1X  (SM_BIAS + 2560)
#define SM_WLIN (SM_W1X + 1280)
#define SM_X    (SM_WLIN + 320)             // 2 x 32 f32
#define SM_PART (SM_X + 256)                // 128 f32
#define SMEM_TOTAL (SM_PART + 512 + 64)     // ~155 KB

// packed weights: 3 blocks [320][KA1]: 0=w_hh1, 1=w_ih2, 2=w_hh2
__device__ __align__(16) __half g_Wh[3 * 320 * KA1];

static __device__ __forceinline__ uint32_t smem_u32(const void *p) {
    uint32_t a;
    asm("{ .reg .u64 t; cvta.to.shared.u64 t, %1; cvt.u32.u64 %0, t; }" : "=r"(a) : "l"(p));
    return a;
}
static __device__ __forceinline__ float tanhap(float x) {
    float y; asm("tanh.approx.f32 %0, %1;" : "=f"(y) : "f"(x)); return y;
}
static __device__ __forceinline__ float sigf(float x) {
    return fmaf(0.5f, tanhap(0.5f * x), 0.5f);
}

#define LDSM_X4(r0, r1, r2, r3, addr) \
    asm volatile("ldmatrix.sync.aligned.m8n8.x4.shared.b16 {%0,%1,%2,%3}, [%4];" \
                 : "=r"(r0), "=r"(r1), "=r"(r2), "=r"(r3) : "r"(addr))
#define LDSM_X2(r0, r1, addr) \
    asm volatile("ldmatrix.sync.aligned.m8n8.x2.shared.b16 {%0,%1}, [%2];" \
                 : "=r"(r0), "=r"(r1) : "r"(addr))
#define MMA16816(d, a0, a1, a2, a3, b0, b1) \
    asm volatile("mma.sync.aligned.m16n8k16.row.col.f32.f16.f16.f32 " \
                 "{%0,%1,%2,%3}, {%4,%5,%6,%7}, {%8,%9}, {%0,%1,%2,%3};" \
                 : "+f"((d)[0]), "+f"((d)[1]), "+f"((d)[2]), "+f"((d)[3]) \
                 : "r"(a0), "r"(a1), "r"(a2), "r"(a3), "r"(b0), "r"(b1))

// ---------------------------------------------------------------------------
__global__ void pack_w_kernel(const float *__restrict__ whh1,
                              const float *__restrict__ wih2,
                              const float *__restrict__ whh2) {
    int idx = blockIdx.x * blockDim.x + threadIdx.x;
    if (idx >= 3 * 320 * KA1) return;
    int blk = idx / (320 * KA1), rem = idx % (320 * KA1);
    int gr = rem / KA1, k = rem % KA1;
    int g = gr & 3, j = gr >> 2;
    int row = g * 80 + j;
    float v = 0.0f;
    if (k < 80) {
        const float *src = (blk == 0) ? whh1 : (blk == 1) ? wih2 : whh2;
        v = src[row * 80 + k];
    }
    g_Wh[idx] = __float2half_rn(v);
}

// 5-chunk gemm with register-resident A frags; B at byte offset KBOFF
template<int CF, int KBOFF>
static __device__ __forceinline__ void gemm5f(const uint32_t (&aF)[10][2][4],
                                              uint32_t bB, float (&d)[2][4][4]) {
#pragma unroll
    for (int c = 0; c < 5; c++) {
        uint32_t b0[4], b1[4];
#pragma unroll
        for (int nt = 0; nt < 4; nt++)
            LDSM_X2(b0[nt], b1[nt], bB + nt * (8 * KB * 2) + KBOFF + c * 32);
#pragma unroll
        for (int nt = 0; nt < 4; nt++) {
            MMA16816(d[0][nt], aF[CF + c][0][0], aF[CF + c][0][1],
                     aF[CF + c][0][2], aF[CF + c][0][3], b0[nt], b1[nt]);
            MMA16816(d[1][nt], aF[CF + c][1][0], aF[CF + c][1][1],
                     aF[CF + c][1][2], aF[CF + c][1][3], b0[nt], b1[nt]);
        }
    }
}

// gemm1: K=80, A via LDSM from SM_W1
static __device__ __forceinline__ void gemm1(uint32_t aB0, uint32_t aB1,
                                             uint32_t bB, float (&d)[2][4][4]) {
#pragma unroll
    for (int m = 0; m < 2; m++)
#pragma unroll
        for (int n = 0; n < 4; n++)
#pragma unroll
            for (int q = 0; q < 4; q++) d[m][n][q] = 0.0f;
#pragma unroll
    for (int c = 0; c < 5; c++) {
        uint32_t a0, a1, a2, a3, e0, e1, e2, e3;
        LDSM_X4(a0, a1, a2, a3, aB0 + c * 32);
        LDSM_X4(e0, e1, e2, e3, aB1 + c * 32);
        uint32_t b0[4], b1[4];
#pragma unroll
        for (int nt = 0; nt < 4; nt++)
            LDSM_X2(b0[nt], b1[nt], bB + nt * (8 * KB * 2) + c * 32);
#pragma unroll
        for (int nt = 0; nt < 4; nt++) {
            MMA16816(d[0][nt], a0, a1, a2, a3, b0[nt], b1[nt]);
            MMA16816(d[1][nt], e0, e1, e2, e3, b0[nt], b1[nt]);
        }
    }
}

// epilogue: D fragments -> gates smem transposed [r][gr]
static __device__ __forceinline__ void epi(float *gf, const float (&d)[2][4][4],
                                           int mt0, int lid) {
    const int g = lid >> 2, tg = lid & 3;
#pragma unroll
    for (int m = 0; m < 2; m++) {
        const int gr = (mt0 + m) * 16 + g;
#pragma unroll
        for (int nt = 0; nt < 4; nt++) {
            const int r = nt * 8 + 2 * tg;
            gf[r * GS + gr]           = d[m][nt][0];
            gf[(r + 1) * GS + gr]     = d[m][nt][1];
            gf[r * GS + gr + 8]       = d[m][nt][2];
            gf[(r + 1) * GS + gr + 8] = d[m][nt][3];
        }
    }
}

// cell: layer l; gates from gf; thread (j=tid%80) does 8 rows; writes h fp16
static __device__ __forceinline__ void cellp(char *smem, const float *gf, int tid,
                                             int l, const float *xbuf, float (&cst)[8]) {
    const int j  = tid % 80;
    const int r0 = (tid / 80) * 8;
    const float4 bb = ((const float4 *)(smem + SM_BIAS))[l * 80 + j];
    float4 wx = make_float4(0.f, 0.f, 0.f, 0.f);
    if (l == 0) wx = ((const float4 *)(smem + SM_W1X))[j];
    const int kk = (l == 0) ? j : (80 + j);
    __half *hb = (__half *)(smem + SM_B);
#pragma unroll
    for (int dr = 0; dr < 8; dr++) {
        const int r = r0 + dr;
        const float4 gv = *(const float4 *)(gf + r * GS + 4 * j);
        float iv = gv.x + bb.x, fv = gv.y + bb.y;
        float gg = gv.z + bb.z, ov = gv.w + bb.w;
        if (l == 0) {
            const float xr = xbuf[r];
            iv = fmaf(wx.x, xr, iv); fv = fmaf(wx.y, xr, fv);
            gg = fmaf(wx.z, xr, gg); ov = fmaf(wx.w, xr, ov);
        }
        const float cc = sigf(fv) * cst[dr] + sigf(iv) * tanhap(gg);
        cst[dr] = cc;
        hb[r * KB + kk] = __float2half_rn(sigf(ov) * tanhap(cc));
    }
}

static __device__ __forceinline__ void head_part(char *smem, int tid) {
    if (tid >= 128) return;
    const int q = tid >> 5, r = tid & 31;
    const __half *hb = (const __half *)(smem + SM_B);
    const float *wlin_s = (const float *)(smem + SM_WLIN);
    float s = 0.0f;
#pragma unroll
    for (int jj = 0; jj < 20; jj++) {
        const int j = q * 20 + jj;
        s = fmaf(wlin_s[j], __half2float(hb[r * KB + 80 + j]), s);
    }
    ((float *)(smem + SM_PART))[q * 32 + r] = s;
}
static __device__ __forceinline__ void head_red(char *smem, int tid, float blin_v,
                                                float *out, int srow, int tOut) {
    if (tid >= NROW) return;
    const float *part = (const float *)(smem + SM_PART);
    out[srow * T + tOut] =
        blin_v + part[tid] + part[32 + tid] + part[64 + tid] + part[96 + tid];
}

// ---------------------------------------------------------------------------
__global__ void __launch_bounds__(NTHR, 1)
lstm_mma_kernel(const float *__restrict__ input,
                const float *__restrict__ w_ih1,
                const float *__restrict__ b_ih1, const float *__restrict__ b_hh1,
                const float *__restrict__ b_ih2, const float *__restrict__ b_hh2,
                const float *__restrict__ w_lin, const float *__restrict__ b_lin,
                float *__restrict__ out) {
    extern __shared__ char smem[];
    const int tid = threadIdx.x;
    const int wid = tid >> 5;
    const int lid = tid & 31;
    const int b0  = blockIdx.x * NROW;
    const uint32_t sb = smem_u32(smem);

    // per-thread ldmatrix geometry
    const int mt0 = wid * 2;
    const uint32_t aRow = (uint32_t)((lid & 7) + ((lid >> 3) & 1) * 8);
    const uint32_t aK8  = (uint32_t)(((lid >> 4) & 1) * 8);
    const uint32_t aB0  = sb + SM_W1 + ((mt0 * 16 + aRow) * KA1 + aK8) * 2;
    const uint32_t aB1  = aB0 + 16 * KA1 * 2;
    const uint32_t bRow = (uint32_t)(lid & 7);
    const uint32_t bK8  = (uint32_t)(((lid >> 3) & 1) * 8);
    const uint32_t bB   = sb + SM_B + (bRow * KB + bK8) * 2;
    const uint32_t sStage = sb + SM_G1 + ((mt0 * 16 + aRow) * KA1 + aK8) * 2;

    // w_hh1 -> SM_W1
    {
        const int4 *s = (const int4 *)g_Wh;
        int4 *dd = (int4 *)(smem + SM_W1);
        for (int i = tid; i < W1_BYTES / 16; i += NTHR) dd[i] = s[i];
    }

    uint32_t aF[10][2][4];
    // stage w_ih2 into gates region, hoist aF[0..4]
    {
        const int4 *s = (const int4 *)(g_Wh + 320 * KA1);
        int4 *dd = (int4 *)(smem + SM_G1);
        for (int i = tid; i < W1_BYTES / 16; i += NTHR) dd[i] = s[i];
    }
    __syncthreads();
#pragma unroll
    for (int c = 0; c < 5; c++) {
        LDSM_X4(aF[c][0][0], aF[c][0][1], aF[c][0][2], aF[c][0][3], sStage + c * 32);
        LDSM_X4(aF[c][1][0], aF[c][1][1], aF[c][1][2], aF[c][1][3],
                sStage + 16 * KA1 * 2 + c * 32);
    }
    __syncthreads();
    // stage w_hh2, hoist aF[5..9]
    {
        const int4 *s = (const int4 *)(g_Wh + 2 * 320 * KA1);
        int4 *dd = (int4 *)(smem + SM_G1);
        for (int i = tid; i < W1_BYTES / 16; i += NTHR) dd[i] = s[i];
    }
    __syncthreads();
#pragma unroll
    for (int c = 0; c < 5; c++) {
        LDSM_X4(aF[5 + c][0][0], aF[5 + c][0][1], aF[5 + c][0][2], aF[5 + c][0][3],
                sStage + c * 32);
        LDSM_X4(aF[5 + c][1][0], aF[5 + c][1][1], aF[5 + c][1][2], aF[5 + c][1][3],
                sStage + 16 * KA1 * 2 + c * 32);
    }
    __syncthreads();

    // zero h buffer, zero G1 (gates1(0)=0 since h1(-1)=0), biases etc.
    {
        int4 z = make_int4(0, 0, 0, 0);
        int4 *dd = (int4 *)(smem + SM_B);
        for (int i = tid; i < B_BYTES / 16; i += NTHR) dd[i] = z;
        float *g1 = (float *)(smem + SM_G1);
        for (int i = tid; i < NROW * GS; i += NTHR) g1[i] = 0.0f;
        float *bias_s = (float *)(smem + SM_BIAS);
        float *w1x_s  = (float *)(smem + SM_W1X);
        for (int i = tid; i < 640; i += NTHR) {
            int l = i / 320, e = i % 320;
            int g = e & 3, j = e >> 2;
            int row = g * 80 + j;
            bias_s[i] = l ? (b_ih2[row] + b_hh2[row]) : (b_ih1[row] + b_hh1[row]);
        }
        for (int i = tid; i < 320; i += NTHR) {
            int g = i & 3, j = i >> 2;
            w1x_s[i] = w_ih1[g * 80 + j];
        }
        if (tid < H) ((float *)(smem + SM_WLIN))[tid] = w_lin[tid];
    }

    float *gf1 = (float *)(smem + SM_G1);
    float *gf2 = (float *)(smem + SM_G2);
    float *xs  = (float *)(smem + SM_X);
    const float blin_v = b_lin[0];
    const int srow = b0 + (tid & 31);

    float c1[8], c2[8];
#pragma unroll
    for (int q = 0; q < 8; q++) { c1[q] = 0.0f; c2[q] = 0.0f; }

    if (tid < NROW) xs[tid] = input[srow * T + 0];
    __syncthreads();

    for (int t = 0; t < T; t++) {
        float xnext = 0.0f;
        if (tid < NROW && t + 1 < T) xnext = input[srow * T + (t + 1)];

        // ---- P1: gemm2-own(t) [h2(t-1)] (tensor) || cell1(t) (MUFU) ----
        float d2[2][4][4];
#pragma unroll
        for (int m = 0; m < 2; m++)
#pragma unroll
            for (int n = 0; n < 4; n++)
#pragma unroll
                for (int q = 0; q < 4; q++) d2[m][n][q] = 0.0f;
        gemm5f<5, 160>(aF, bB, d2);                 // B k=80..160 (h2 old)
        cellp(smem, gf1, tid, 0, xs + (t & 1) * 32, c1);   // h1(t) -> B k=0..80
        __syncthreads();

        // ---- P2: gemm2-in(t) [h1(t)] (tensor) || head_part(t-1) ----
        gemm5f<0, 0>(aF, bB, d2);                   // B k=0..80 (h1 new)
        epi(gf2, d2, mt0, lid);
        if (t > 0) head_part(smem, tid);
        if (tid < NROW && t + 1 < T) xs[((t + 1) & 1) * 32 + tid] = xnext;
        __syncthreads();

        // ---- P3: cell2(t) (MUFU) || gemm1(t+1) [h1(t)] (tensor) || head_red ----
        cellp(smem, gf2, tid, 1, nullptr, c2);      // h2(t) -> B k=80..160
        if (t + 1 < T) {
            float d1[2][4][4];
            gemm1(aB0, aB1, bB, d1);
            epi(gf1, d1, mt0, lid);
        }
        if (t > 0) head_red(smem, tid, blin_v, out, srow, t - 1);
        __syncthreads();
    }

    // epilogue: head for t = T-1
    head_part(smem, tid);
    __syncthreads();
    head_red(smem, tid, blin_v, out, srow, T - 1);
}

extern "C" void kernel_launch(void *const *d_in, const int *in_sizes, int n_in,
                              void *d_out, int out_size) {
    const float *input = (const float *)d_in[0];
    const float *wih1  = (const float *)d_in[1];
    const float *whh1  = (const float *)d_in[2];
    const float *bih1  = (const float *)d_in[3];
    const float *bhh1  = (const float *)d_in[4];
    const float *wih2  = (const float *)d_in[5];
    const float *whh2  = (const float *)d_in[6];
    const float *bih2  = (const float *)d_in[7];
    const float *bhh2  = (const float *)d_in[8];
    const float *wlin  = (const float *)d_in[17];
    const float *blin  = (const float *)d_in[18];

    pack_w_kernel<<<(3 * 320 * KA1 + 255) / 256, 256>>>(whh1, wih2, whh2);

    cudaFuncSetAttribute(lstm_mma_kernel, cudaFuncAttributeMaxDynamicSharedMemorySize,
                         SMEM_TOTAL);
    lstm_mma_kernel<<<NCTA, NTHR, SMEM_TOTAL>>>(input, wih1, bih1, bhh1, bih2, bhh2,
                                                wlin, blin, (float *)d_out);
}

// round 16
// speedup vs baseline: 1.2871x; 1.0197x over previous
#include <cuda_runtime.h>
#include <cuda_fp16.h>
#include <cstdint>

// Problem constants
#define H     80
#define B     4096
#define T     512
#define NROW  32
#define NCTA  128
#define NTHR  640           // 20 warps; warp = (m-pair w=wid>>1, n-half nh=wid&1)

#define KA1   88            // weight smem stride (halves); 176B/16=11 odd -> conflict-free
#define KB    168           // h buffer stride (halves); odd /16
#define GS    324           // gates f32 stride ([r][gr] transposed)

#define WBLK_BYTES (320 * KA1 * 2)   // 56320 per weight block
#define B_BYTES    (NROW * KB * 2)   // 10752
#define G_BYTES    (NROW * GS * 4)   // 41472

// smem offsets (bytes)
#define SM_W1   0                            // w_hh1 (gemm1 A)
#define SM_W2I  (SM_W1 + WBLK_BYTES)         // w_ih2 (gemm2-in A)
#define SM_B    (SM_W2I + WBLK_BYTES)        // h fp16 [32][KB]
#define SM_G1   (SM_B + B_BYTES)             // gates1; also w_hh2 staging at init
#define SM_G2   (SM_G1 + G_BYTES)
#define SM_BIAS (SM_G2 + G_BYTES)
#define SM_W1X  (SM_BIAS + 2560)
#define SM_WLIN (SM_W1X + 1280)
#define SM_X    (SM_WLIN + 320)              // 2 x 32 f32
#define SM_PART (SM_X + 256)                 // 128 f32
#define SMEM_TOTAL (SM_PART + 512 + 64)      // ~212 KB

// packed weights: 3 blocks [320][KA1]: 0=w_hh1, 1=w_ih2, 2=w_hh2
__device__ __align__(16) __half g_Wh[3 * 320 * KA1];

static __device__ __forceinline__ uint32_t smem_u32(const void *p) {
    uint32_t a;
    asm("{ .reg .u64 t; cvta.to.shared.u64 t, %1; cvt.u32.u64 %0, t; }" : "=r"(a) : "l"(p));
    return a;
}
static __device__ __forceinline__ float tanhap(float x) {
    float y; asm("tanh.approx.f32 %0, %1;" : "=f"(y) : "f"(x)); return y;
}
static __device__ __forceinline__ float sigf(float x) {
    return fmaf(0.5f, tanhap(0.5f * x), 0.5f);
}

#define LDSM_X4(r0, r1, r2, r3, addr) \
    asm volatile("ldmatrix.sync.aligned.m8n8.x4.shared.b16 {%0,%1,%2,%3}, [%4];" \
                 : "=r"(r0), "=r"(r1), "=r"(r2), "=r"(r3) : "r"(addr))
#define MMA16816(d, a0, a1, a2, a3, b0, b1) \
    asm volatile("mma.sync.aligned.m16n8k16.row.col.f32.f16.f16.f32 " \
                 "{%0,%1,%2,%3}, {%4,%5,%6,%7}, {%8,%9}, {%0,%1,%2,%3};" \
                 : "+f"((d)[0]), "+f"((d)[1]), "+f"((d)[2]), "+f"((d)[3]) \
                 : "r"(a0), "r"(a1), "r"(a2), "r"(a3), "r"(b0), "r"(b1))

// ---------------------------------------------------------------------------
__global__ void pack_w_kernel(const float *__restrict__ whh1,
                              const float *__restrict__ wih2,
                              const float *__restrict__ whh2) {
    int idx = blockIdx.x * blockDim.x + threadIdx.x;
    if (idx >= 3 * 320 * KA1) return;
    int blk = idx / (320 * KA1), rem = idx % (320 * KA1);
    int gr = rem / KA1, k = rem % KA1;
    int g = gr & 3, j = gr >> 2;
    int row = g * 80 + j;
    float v = 0.0f;
    if (k < 80) {
        const float *src = (blk == 0) ? whh1 : (blk == 1) ? wih2 : whh2;
        v = src[row * 80 + k];
    }
    g_Wh[idx] = __float2half_rn(v);
}

// B-fragments for this warp's 2 n-tiles, one X4 per chunk.
// bX4 lane base encodes (nh, ntl, k8, row); add KBOFF + c*32 bytes.
#define LOAD_B(b00, b10, b01, b11, bX4, OFFB) \
    LDSM_X4(b00, b10, b01, b11, (bX4) + (OFFB))

// gemm 5 chunks, A register-resident (aF), B at byte offset KBOFF
static __device__ __forceinline__ void gemm5_aF(const uint32_t (&aF)[5][2][4],
                                                uint32_t bX4, int KBOFF,
                                                float (&d)[2][2][4]) {
#pragma unroll
    for (int c = 0; c < 5; c++) {
        uint32_t b00, b10, b01, b11;
        LOAD_B(b00, b10, b01, b11, bX4, KBOFF + c * 32);
        MMA16816(d[0][0], aF[c][0][0], aF[c][0][1], aF[c][0][2], aF[c][0][3], b00, b10);
        MMA16816(d[0][1], aF[c][0][0], aF[c][0][1], aF[c][0][2], aF[c][0][3], b01, b11);
        MMA16816(d[1][0], aF[c][1][0], aF[c][1][1], aF[c][1][2], aF[c][1][3], b00, b10);
        MMA16816(d[1][1], aF[c][1][0], aF[c][1][1], aF[c][1][2], aF[c][1][3], b01, b11);
    }
}

// gemm 5 chunks, A via LDSM from aB0/aB1 (k-major, KA1 stride), B at KBOFF.
// ZERO_D: initialize d to zero first.
template<bool ZERO_D>
static __device__ __forceinline__ void gemm5_ld(uint32_t aB0, uint32_t aB1,
                                                uint32_t bX4, int KBOFF,
                                                float (&d)[2][2][4]) {
    if (ZERO_D) {
#pragma unroll
        for (int m = 0; m < 2; m++)
#pragma unroll
            for (int n = 0; n < 2; n++)
#pragma unroll
                for (int q = 0; q < 4; q++) d[m][n][q] = 0.0f;
    }
#pragma unroll
    for (int c = 0; c < 5; c++) {
        uint32_t a0, a1, a2, a3, e0, e1, e2, e3;
        LDSM_X4(a0, a1, a2, a3, aB0 + c * 32);
        LDSM_X4(e0, e1, e2, e3, aB1 + c * 32);
        uint32_t b00, b10, b01, b11;
        LOAD_B(b00, b10, b01, b11, bX4, KBOFF + c * 32);
        MMA16816(d[0][0], a0, a1, a2, a3, b00, b10);
        MMA16816(d[0][1], a0, a1, a2, a3, b01, b11);
        MMA16816(d[1][0], e0, e1, e2, e3, b00, b10);
        MMA16816(d[1][1], e0, e1, e2, e3, b01, b11);
    }
}

// epilogue: D -> gates smem transposed [r][gr]; warp covers 2 mt x 2 nt
static __device__ __forceinline__ void epi(float *gf, const float (&d)[2][2][4],
                                           int mt0, int nh, int lid) {
    const int g = lid >> 2, tg = lid & 3;
#pragma unroll
    for (int m = 0; m < 2; m++) {
        const int gr = (mt0 + m) * 16 + g;
#pragma unroll
        for (int ntl = 0; ntl < 2; ntl++) {
            const int r = (2 * nh + ntl) * 8 + 2 * tg;
            gf[r * GS + gr]           = d[m][ntl][0];
            gf[(r + 1) * GS + gr]     = d[m][ntl][1];
            gf[r * GS + gr + 8]       = d[m][ntl][2];
            gf[(r + 1) * GS + gr + 8] = d[m][ntl][3];
        }
    }
}

// cell: 640 threads; thread (j=tid%80, grp=tid/80) does 4 rows grp*4..+3
static __device__ __forceinline__ void cellp(char *smem, const float *gf, int tid,
                                             int l, const float *xbuf, float (&cst)[4]) {
    const int j  = tid % 80;
    const int r0 = (tid / 80) * 4;
    const float4 bb = ((const float4 *)(smem + SM_BIAS))[l * 80 + j];
    float4 wx = make_float4(0.f, 0.f, 0.f, 0.f);
    if (l == 0) wx = ((const float4 *)(smem + SM_W1X))[j];
    const int kk = (l == 0) ? j : (80 + j);
    __half *hb = (__half *)(smem + SM_B);
#pragma unroll
    for (int dr = 0; dr < 4; dr++) {
        const int r = r0 + dr;
        const float4 gv = *(const float4 *)(gf + r * GS + 4 * j);
        float iv = gv.x + bb.x, fv = gv.y + bb.y;
        float gg = gv.z + bb.z, ov = gv.w + bb.w;
        if (l == 0) {
            const float xr = xbuf[r];
            iv = fmaf(wx.x, xr, iv); fv = fmaf(wx.y, xr, fv);
            gg = fmaf(wx.z, xr, gg); ov = fmaf(wx.w, xr, ov);
        }
        const float cc = sigf(fv) * cst[dr] + sigf(iv) * tanhap(gg);
        cst[dr] = cc;
        hb[r * KB + kk] = __float2half_rn(sigf(ov) * tanhap(cc));
    }
}

static __device__ __forceinline__ void head_part(char *smem, int tid) {
    if (tid >= 128) return;
    const int q = tid >> 5, r = tid & 31;
    const __half *hb = (const __half *)(smem + SM_B);
    const float *wlin_s = (const float *)(smem + SM_WLIN);
    float s = 0.0f;
#pragma unroll
    for (int jj = 0; jj < 20; jj++) {
        const int j = q * 20 + jj;
        s = fmaf(wlin_s[j], __half2float(hb[r * KB + 80 + j]), s);
    }
    ((float *)(smem + SM_PART))[q * 32 + r] = s;
}
static __device__ __forceinline__ void head_red(char *smem, int tid, float blin_v,
                                                float *out, int srow, int tOut) {
    if (tid >= NROW) return;
    const float *part = (const float *)(smem + SM_PART);
    out[srow * T + tOut] =
        blin_v + part[tid] + part[32 + tid] + part[64 + tid] + part[96 + tid];
}

// ---------------------------------------------------------------------------
__global__ void __launch_bounds__(NTHR, 1)
lstm_mma_kernel(const float *__restrict__ input,
                const float *__restrict__ w_ih1,
                const float *__restrict__ b_ih1, const float *__restrict__ b_hh1,
                const float *__restrict__ b_ih2, const float *__restrict__ b_hh2,
                const float *__restrict__ w_lin, const float *__restrict__ b_lin,
                float *__restrict__ out) {
    extern __shared__ char smem[];
    const int tid = threadIdx.x;
    const int wid = tid >> 5;
    const int lid = tid & 31;
    const int b0  = blockIdx.x * NROW;
    const uint32_t sb = smem_u32(smem);

    // warp role: m-pair w, n-half nh
    const int wmp = wid >> 1;          // 0..9
    const int nh  = wid & 1;           // 0..1
    const int mt0 = wmp * 2;

    // A ldmatrix lane geometry (16x16 tile, K-major, stride KA1)
    const uint32_t aRow = (uint32_t)((lid & 7) + ((lid >> 3) & 1) * 8);
    const uint32_t aK8  = (uint32_t)(((lid >> 4) & 1) * 8);
    const uint32_t aOff = ((mt0 * 16 + aRow) * KA1 + aK8) * 2;
    const uint32_t aW1_0 = sb + SM_W1  + aOff;               // gemm1 mt0
    const uint32_t aW1_1 = aW1_0 + 16 * KA1 * 2;             // gemm1 mt0+1
    const uint32_t aW2_0 = sb + SM_W2I + aOff;               // gemm2-in mt0
    const uint32_t aW2_1 = aW2_0 + 16 * KA1 * 2;
    const uint32_t sStage = sb + SM_G1 + aOff;               // w_hh2 staging

    // B ldmatrix X4 lane geometry: (ntl = lid>>4, k8 = (lid>>3)&1, row = lid&7)
    const uint32_t bNtl = (uint32_t)((lid >> 4) & 1);
    const uint32_t bK8b = (uint32_t)(((lid >> 3) & 1) * 16);   // 8 halves = 16 bytes
    const uint32_t bRow = (uint32_t)(lid & 7);
    const uint32_t bX4  = sb + SM_B +
                          ((2 * (uint32_t)nh + bNtl) * 8 + bRow) * (KB * 2) + bK8b;

    // ---- init: copy weight blocks ----
    {
        const int4 *s0 = (const int4 *)g_Wh;
        int4 *d0 = (int4 *)(smem + SM_W1);
        for (int i = tid; i < WBLK_BYTES / 16; i += NTHR) d0[i] = s0[i];
        const int4 *s1 = (const int4 *)(g_Wh + 320 * KA1);
        int4 *d1 = (int4 *)(smem + SM_W2I);
        for (int i = tid; i < WBLK_BYTES / 16; i += NTHR) d1[i] = s1[i];
        const int4 *s2 = (const int4 *)(g_Wh + 2 * 320 * KA1);
        int4 *d2s = (int4 *)(smem + SM_G1);                  // stage w_hh2
        for (int i = tid; i < WBLK_BYTES / 16; i += NTHR) d2s[i] = s2[i];
        float *bias_s = (float *)(smem + SM_BIAS);
        float *w1x_s  = (float *)(smem + SM_W1X);
        for (int i = tid; i < 640; i += NTHR) {
            int l = i / 320, e = i % 320;
            int g = e & 3, j = e >> 2;
            int row = g * 80 + j;
            bias_s[i] = l ? (b_ih2[row] + b_hh2[row]) : (b_ih1[row] + b_hh1[row]);
        }
        for (int i = tid; i < 320; i += NTHR) {
            int g = i & 3, j = i >> 2;
            w1x_s[i] = w_ih1[g * 80 + j];
        }
        if (tid < H) ((float *)(smem + SM_WLIN))[tid] = w_lin[tid];
    }
    __syncthreads();

    // hoist w_hh2 fragments (gemm2-own), 5 chunks resident
    uint32_t aF[5][2][4];
#pragma unroll
    for (int c = 0; c < 5; c++) {
        LDSM_X4(aF[c][0][0], aF[c][0][1], aF[c][0][2], aF[c][0][3], sStage + c * 32);
        LDSM_X4(aF[c][1][0], aF[c][1][1], aF[c][1][2], aF[c][1][3],
                sStage + 16 * KA1 * 2 + c * 32);
    }
    __syncthreads();

    // zero h buffer and G1 (gates1(0)=0 since h1(-1)=0)
    {
        int4 z = make_int4(0, 0, 0, 0);
        int4 *dd = (int4 *)(smem + SM_B);
        for (int i = tid; i < B_BYTES / 16; i += NTHR) dd[i] = z;
        float *g1 = (float *)(smem + SM_G1);
        for (int i = tid; i < NROW * GS; i += NTHR) g1[i] = 0.0f;
    }

    float *gf1 = (float *)(smem + SM_G1);
    float *gf2 = (float *)(smem + SM_G2);
    float *xs  = (float *)(smem + SM_X);
    const float blin_v = b_lin[0];
    const int srow = b0 + (tid & 31);

    float c1[4], c2[4];
#pragma unroll
    for (int q = 0; q < 4; q++) { c1[q] = 0.0f; c2[q] = 0.0f; }

    if (tid < NROW) xs[tid] = input[srow * T + 0];
    __syncthreads();

    for (int t = 0; t < T; t++) {
        float xnext = 0.0f;
        if (tid < NROW && t + 1 < T) xnext = input[srow * T + (t + 1)];

        // ---- P1: gemm2-own(t) [W_hh2 @ h2(t-1)] (aF, tensor) || cell1(t) (MUFU) ----
        float d2[2][2][4];
#pragma unroll
        for (int m = 0; m < 2; m++)
#pragma unroll
            for (int n = 0; n < 2; n++)
#pragma unroll
                for (int q = 0; q < 4; q++) d2[m][n][q] = 0.0f;
        gemm5_aF(aF, bX4, 160, d2);                          // B k=80..160 (h2 old)
        cellp(smem, gf1, tid, 0, xs + (t & 1) * 32, c1);     // h1(t) -> B k=0..80
        __syncthreads();

        // ---- P2: gemm2-in(t) [W_ih2 @ h1(t)] (LDSM A) || head_part(t-1) ----
        gemm5_ld<false>(aW2_0, aW2_1, bX4, 0, d2);           // B k=0..80 (h1 new)
        epi(gf2, d2, mt0, nh, lid);
        if (t > 0) head_part(smem, tid);
        if (tid < NROW && t + 1 < T) xs[((t + 1) & 1) * 32 + tid] = xnext;
        __syncthreads();

        // ---- P3: cell2(t) (MUFU) || gemm1(t+1) (tensor) || head_red(t-1) ----
        cellp(smem, gf2, tid, 1, nullptr, c2);               // h2(t) -> B k=80..160
        if (t + 1 < T) {
            float d1[2][2][4];
            gemm5_ld<true>(aW1_0, aW1_1, bX4, 0, d1);        // W_hh1 @ h1(t)
            epi(gf1, d1, mt0, nh, lid);
        }
        if (t > 0) head_red(smem, tid, blin_v, out, srow, t - 1);
        __syncthreads();
    }

    // epilogue: head for t = T-1
    head_part(smem, tid);
    __syncthreads();
    head_red(smem, tid, blin_v, out, srow, T - 1);
}

extern "C" void kernel_launch(void *const *d_in, const int *in_sizes, int n_in,
                              void *d_out, int out_size) {
    const float *input = (const float *)d_in[0];
    const float *wih1  = (const float *)d_in[1];
    const float *whh1  = (const float *)d_in[2];
    const float *bih1  = (const float *)d_in[3];
    const float *bhh1  = (const float *)d_in[4];
    const float *wih2  = (const float *)d_in[5];
    const float *whh2  = (const float *)d_in[6];
    const float *bih2  = (const float *)d_in[7];
    const float *bhh2  = (const float *)d_in[8];
    const float *wlin  = (const float *)d_in[17];
    const float *blin  = (const float *)d_in[18];

    pack_w_kernel<<<(3 * 320 * KA1 + 255) / 256, 256>>>(whh1, wih2, whh2);

    cudaFuncSetAttribute(lstm_mma_kernel, cudaFuncAttributeMaxDynamicSharedMemorySize,
                         SMEM_TOTAL);
    lstm_mma_kernel<<<NCTA, NTHR, SMEM_TOTAL>>>(input, wih1, bih1, bhh1, bih2, bhh2,
                                                wlin, blin, (float *)d_out);
}